// round 13
// baseline (speedup 1.0000x reference)
#include <cuda_runtime.h>
#include <cuda_fp16.h>
#include <cstdint>

#define HH 56
#define WW 56
#define NPIX (4 * 56 * 56)   // 12544

// Scratch (device globals — no allocation allowed). fp16 interchange format.
__device__ __align__(16) __half g_qkv[NPIX * 384];   // [pix][3*128] (q|k|v)
__device__ __align__(16) __half g_att[NPIX * 128];   // attention output

// ---------------------------------------------------------------------------
// helpers
// ---------------------------------------------------------------------------
__device__ __forceinline__ void mma16(float* c, const uint32_t* a, const uint32_t* b) {
    asm volatile(
        "mma.sync.aligned.m16n8k16.row.col.f32.f16.f16.f32 "
        "{%0,%1,%2,%3}, {%4,%5,%6,%7}, {%8,%9}, {%0,%1,%2,%3};"
        : "+f"(c[0]), "+f"(c[1]), "+f"(c[2]), "+f"(c[3])
        : "r"(a[0]), "r"(a[1]), "r"(a[2]), "r"(a[3]), "r"(b[0]), "r"(b[1]));
}
__device__ __forceinline__ void ldm4(uint32_t* r, uint32_t addr) {
    asm volatile("ldmatrix.sync.aligned.m8n8.x4.shared.b16 {%0,%1,%2,%3}, [%4];"
                 : "=r"(r[0]), "=r"(r[1]), "=r"(r[2]), "=r"(r[3]) : "r"(addr));
}
__device__ __forceinline__ void ldm4t(uint32_t* r, uint32_t addr) {
    asm volatile("ldmatrix.sync.aligned.m8n8.x4.trans.shared.b16 {%0,%1,%2,%3}, [%4];"
                 : "=r"(r[0]), "=r"(r[1]), "=r"(r[2]), "=r"(r[3]) : "r"(addr));
}
__device__ __forceinline__ uint32_t h22u(__half2 h) {
    return *reinterpret_cast<uint32_t*>(&h);
}

// ---------------------------------------------------------------------------
// Persistent-column fp16 GEMM + bias, 512 threads, 16 warps as 4m x 4n,
// MT=2 register blocking (each warp: 32 rows x WN cols):
//   C[M,N] = A[M,128] @ W[k=128][N] + bias
// Grid (N/BN, 49). Block loads its W column to smem ONCE, then 2 m-tiles of
// 128 rows, double-buffered A staging. All layouts/addressing R10-validated.
// Per k-step per warp: 2 ldm4 (A) + NP ldm4t (B) -> 2*NT mma.
// ---------------------------------------------------------------------------
template <int BN, bool AHALF, bool OUTHALF>
__global__ __launch_bounds__(512, 1)
void gemm_col(const void* __restrict__ Av, const float* __restrict__ Wf,
              const float* __restrict__ bias, void* __restrict__ Cv, int N)
{
    constexpr int WN = BN / 4;                 // n cols per warp (32 or 16)
    constexpr int NP = (WN + 15) / 16;         // n16 ldmatrix tiles per warp
    constexpr int NT = WN / 8;                 // mma n tiles per warp
    constexpr int WCS = 2576;                  // W chunk stride (words)
    constexpr int AB = 4 * 128 * 20;           // words per A buffer (4 k-chunks)

    extern __shared__ uint32_t smg[];
    uint32_t* sA = smg;                        // 2 buffers of AB
    uint32_t* sW = smg + 2 * AB;

    const int t = threadIdx.x, w = t >> 5, lane = t & 31;
    const int wm = w & 3, wn = w >> 2;
    const int lr = lane >> 2, lc = lane & 3;
    const int lt = lane >> 3, rw = lane & 7;
    const int bn = blockIdx.x * BN;
    const int mbase = blockIdx.y * 256;        // 2 tiles of 128 rows

    // ---- stage W once: [k][n] -> chunked halves ----
    {
        constexpr int WU = (128 * (BN / 8)) / 512;
#pragma unroll
        for (int u = 0; u < WU; u++) {
            int g = t + 512 * u;
            int k = g / (BN / 8), ni = g % (BN / 8);
            const float* Wp = Wf + (size_t)k * N + bn + ni * 8;
            float4 f0 = *(const float4*)(Wp);
            float4 f1 = *(const float4*)(Wp + 4);
            uint4 v;
            v.x = h22u(__floats2half2_rn(f0.x, f0.y));
            v.y = h22u(__floats2half2_rn(f0.z, f0.w));
            v.z = h22u(__floats2half2_rn(f1.x, f1.y));
            v.w = h22u(__floats2half2_rn(f1.z, f1.w));
            *(uint4*)(sW + (ni >> 2) * WCS + k * 20 + (ni & 3) * 4) = v;
        }
    }

    // per-lane fragment addresses (validated patterns)
    const uint32_t smb = (uint32_t)__cvta_generic_to_shared(smg);
    uint32_t aPat[2];
#pragma unroll
    for (int mt = 0; mt < 2; mt++)
        aPat[mt] = ((wm * 32 + mt * 16 + (lt & 1) * 8 + rw) * 20
                    + (lt >> 1) * 4) * 4;
    const uint32_t vpat = ((((lane >> 3) & 1) * 8 + (lane & 7)) * 20
                           + (lane >> 4) * 4) * 4;
    uint32_t bAddr[NP];
#pragma unroll
    for (int p = 0; p < NP; p++) {
        int n0 = wn * WN + p * 16;
        bAddr[p] = smb + (2 * AB + (n0 >> 5) * WCS) * 4 + vpat
                   + ((n0 & 16) ? 32 : 0);
    }
    // bias registers (fixed columns per warp)
    float bs0[NT], bs1[NT];
#pragma unroll
    for (int nt = 0; nt < NT; nt++) {
        int c = bn + wn * WN + nt * 8 + lc * 2;
        bs0[nt] = bias[c];
        bs1[nt] = bias[c + 1];
    }

    // A staging registers (512 threads cover 128 rows x 16 uint4)
    const int arow = t >> 2, aseg = t & 3;
    float4 aF[8];
    uint4 aH[4];

    auto ldg_tile = [&](int m) {
        if constexpr (!AHALF) {
            const float* Ap = (const float*)Av
                + (size_t)(mbase + m * 128 + arow) * 128 + aseg * 8;
#pragma unroll
            for (int s = 0; s < 4; s++) {
                aF[2 * s]     = *(const float4*)(Ap + s * 32);
                aF[2 * s + 1] = *(const float4*)(Ap + s * 32 + 4);
            }
        } else {
            const __half* Ap = (const __half*)Av
                + (size_t)(mbase + m * 128 + arow) * 128 + aseg * 8;
#pragma unroll
            for (int s = 0; s < 4; s++)
                aH[s] = *(const uint4*)(Ap + s * 32);
        }
    };
    auto sts_tile = [&](int m) {
        uint32_t* dst = sA + (m & 1) * AB + arow * 20 + aseg * 4;
        if constexpr (!AHALF) {
#pragma unroll
            for (int s = 0; s < 4; s++) {
                uint4 v;
                v.x = h22u(__floats2half2_rn(aF[2 * s].x, aF[2 * s].y));
                v.y = h22u(__floats2half2_rn(aF[2 * s].z, aF[2 * s].w));
                v.z = h22u(__floats2half2_rn(aF[2 * s + 1].x, aF[2 * s + 1].y));
                v.w = h22u(__floats2half2_rn(aF[2 * s + 1].z, aF[2 * s + 1].w));
                *(uint4*)(dst + s * 2560) = v;
            }
        } else {
#pragma unroll
            for (int s = 0; s < 4; s++)
                *(uint4*)(dst + s * 2560) = aH[s];
        }
    };

    ldg_tile(0);

#pragma unroll 1
    for (int m = 0; m < 2; m++) {
        sts_tile(m);
        __syncthreads();
        if (m < 1) ldg_tile(m + 1);

        float acc[2][NT][4];
#pragma unroll
        for (int mt = 0; mt < 2; mt++)
#pragma unroll
            for (int nt = 0; nt < NT; nt++)
#pragma unroll
                for (int i = 0; i < 4; i++) acc[mt][nt][i] = 0.f;

        const uint32_t aBase = smb + (m & 1) * AB * 4;
#pragma unroll
        for (int s = 0; s < 8; s++) {
            uint32_t af[2][4], bf[NT][2];
            ldm4(af[0], aBase + aPat[0] + (s >> 1) * 10240 + (s & 1) * 32);
            ldm4(af[1], aBase + aPat[1] + (s >> 1) * 10240 + (s & 1) * 32);
#pragma unroll
            for (int p = 0; p < NP; p++) {
                uint32_t r4[4];
                ldm4t(r4, bAddr[p] + s * 1280);
                bf[2 * p][0] = r4[0]; bf[2 * p][1] = r4[1];
                bf[2 * p + 1][0] = r4[2]; bf[2 * p + 1][1] = r4[3];
            }
#pragma unroll
            for (int mt = 0; mt < 2; mt++)
#pragma unroll
                for (int nt = 0; nt < NT; nt++)
                    mma16(acc[mt][nt], af[mt], bf[nt]);
        }

        // epilogue with bias
#pragma unroll
        for (int mt = 0; mt < 2; mt++) {
            const int r0 = mbase + m * 128 + wm * 32 + mt * 16 + lr;
#pragma unroll
            for (int nt = 0; nt < NT; nt++) {
                int c = bn + wn * WN + nt * 8 + lc * 2;
                if constexpr (OUTHALF) {
                    __half* Ch = (__half*)Cv;
                    *(__half2*)(Ch + (size_t)r0 * N + c) =
                        __floats2half2_rn(acc[mt][nt][0] + bs0[nt],
                                          acc[mt][nt][1] + bs1[nt]);
                    *(__half2*)(Ch + (size_t)(r0 + 8) * N + c) =
                        __floats2half2_rn(acc[mt][nt][2] + bs0[nt],
                                          acc[mt][nt][3] + bs1[nt]);
                } else {
                    float* Cf = (float*)Cv;
                    *(float2*)(Cf + (size_t)r0 * N + c) =
                        make_float2(acc[mt][nt][0] + bs0[nt],
                                    acc[mt][nt][1] + bs1[nt]);
                    *(float2*)(Cf + (size_t)(r0 + 8) * N + c) =
                        make_float2(acc[mt][nt][2] + bs0[nt],
                                    acc[mt][nt][3] + bs1[nt]);
                }
            }
        }
    }
}

// ---------------------------------------------------------------------------
// Streaming flash-style neighborhood attention (R7-validated, verbatim).
// ---------------------------------------------------------------------------
#define SQ_OFF 0
#define SK_OFF (64 * 20)
#define SV_OFF (SK_OFF + 208 * 20)
#define SM_WORDS (SV_OFF + 208 * 20)

__global__ __launch_bounds__(128)
void natten_kernel(const __half* __restrict__ qkv, const float* __restrict__ rpb)
{
    __shared__ __align__(16) uint32_t sm[SM_WORDS];
    __shared__ float rp[169];

    const int tile = blockIdx.x;             // 0..48
    const int ti = tile / 7, tj = tile % 7;
    const int h = blockIdx.y, b = blockIdx.z;
    const int i0 = ti * 8, j0 = tj * 8;
    const int r0 = min(max(i0 - 3, 0), HH - 14);
    const int c0 = min(max(j0 - 3, 0), WW - 14);
    const int tid = threadIdx.x;

    for (int e = tid; e < 169; e += 128) rp[e] = rpb[h * 169 + e];

#pragma unroll
    for (int e = tid; e < 256; e += 128) {
        int row = e >> 2, seg = e & 3;
        int qi = row >> 3, qj = row & 7;
        size_t pix = (size_t)((b * HH + i0 + qi) * WW + j0 + qj);
        *(uint4*)(sm + SQ_OFF + row * 20 + seg * 4) =
            *(const uint4*)(qkv + pix * 384 + h * 32 + seg * 8);
    }
    for (int e = tid; e < 784; e += 128) {
        int row = e >> 2, seg = e & 3;
        int r = row / 14, c = row - r * 14;
        size_t pix = (size_t)((b * HH + r0 + r) * WW + c0 + c);
        const __half* base = qkv + pix * 384 + h * 32;
        *(uint4*)(sm + SK_OFF + row * 20 + seg * 4) = *(const uint4*)(base + 128 + seg * 8);
        *(uint4*)(sm + SV_OFF + row * 20 + seg * 4) = *(const uint4*)(base + 256 + seg * 8);
    }
    for (int e = tid; e < 240; e += 128) {
        sm[SK_OFF + 3920 + e] = 0;
        sm[SV_OFF + 3920 + e] = 0;
    }
    __syncthreads();

    const int w = tid >> 5, lane = tid & 31;
    const int lr = lane >> 2, lc = lane & 3;
    const int lt = lane >> 3, rw = lane & 7;

    const uint32_t base = (uint32_t)__cvta_generic_to_shared(sm);
    const uint32_t aAddr = base + SQ_OFF * 4
        + ((w * 16 + (lt & 1) * 8 + rw) * 20 + ((lt >> 1) << 2)) * 4;
    const uint32_t kAddr = base + SK_OFF * 4
        + ((((lt >> 1) << 3) + rw) * 20 + ((lt & 1) << 2)) * 4;
    const uint32_t vAddr = base + SV_OFF * 4
        + (((((lane >> 3) & 1) << 3) + (lane & 7)) * 20 + ((lane >> 4) << 2)) * 4;

    uint32_t af0[4], af1[4];
    ldm4(af0, aAddr);
    ldm4(af1, aAddr + 32);

    const int i_lo = i0 + 2 * w, i_hi = i_lo + 1;
    const int j = j0 + lr;
    const int kri_lo = min(max(i_lo - 3, 0), HH - 7) - r0;
    const int kri_hi = min(max(i_hi - 3, 0), HH - 7) - r0;
    const int kcj = min(max(j - 3, 0), WW - 7) - c0;
    const int ci_lo = 6 - (i_lo - r0);
    const int ci_hi = 6 - (i_hi - r0);
    const int cj = 6 - (j - c0);
    const float scale = 0.17677669529663687f;   // 32^-0.5

    float out[4][4];
#pragma unroll
    for (int nt = 0; nt < 4; nt++)
#pragma unroll
        for (int i = 0; i < 4; i++) out[nt][i] = 0.f;
    float l_lo = 0.f, l_hi = 0.f;

#pragma unroll
    for (int t2 = 0; t2 < 13; t2++) {
        float sacc[2][4];
#pragma unroll
        for (int tt = 0; tt < 2; tt++)
#pragma unroll
            for (int i = 0; i < 4; i++) sacc[tt][i] = 0.f;
        {
            uint32_t r4[4];
            ldm4(r4, kAddr + t2 * 1280);
            mma16(sacc[0], af0, r4);
            mma16(sacc[1], af0, r4 + 2);
            ldm4(r4, kAddr + t2 * 1280 + 32);
            mma16(sacc[0], af1, r4);
            mma16(sacc[1], af1, r4 + 2);
        }
#pragma unroll
        for (int tt = 0; tt < 2; tt++) {
#pragma unroll
            for (int c = 0; c < 2; c++) {
                int key = (2 * t2 + tt) * 8 + 2 * lc + c;
                int kr = (key * 2341) >> 15;
                int kc = key - kr * 14;
                bool vC = (unsigned)(kc - kcj) < 7u;
                int cb = kc + cj;

                bool v1 = vC && ((unsigned)(kr - kri_lo) < 7u);
                int idx1 = min(max((kr + ci_lo) * 13 + cb, 0), 168);
                float e1 = __expf(v1 ? fmaf(sacc[tt][c], scale, rp[idx1]) : -60.f);
                sacc[tt][c] = e1;
                l_lo += e1;

                bool v2 = vC && ((unsigned)(kr - kri_hi) < 7u);
                int idx2 = min(max((kr + ci_hi) * 13 + cb, 0), 168);
                float e2 = __expf(v2 ? fmaf(sacc[tt][2 + c], scale, rp[idx2]) : -60.f);
                sacc[tt][2 + c] = e2;
                l_hi += e2;
            }
        }
        uint32_t pa[4];
        pa[0] = h22u(__floats2half2_rn(sacc[0][0], sacc[0][1]));
        pa[1] = h22u(__floats2half2_rn(sacc[0][2], sacc[0][3]));
        pa[2] = h22u(__floats2half2_rn(sacc[1][0], sacc[1][1]));
        pa[3] = h22u(__floats2half2_rn(sacc[1][2], sacc[1][3]));

        uint32_t b0[4], b1[4];
        ldm4t(b0, vAddr + t2 * 1280);
        ldm4t(b1, vAddr + t2 * 1280 + 32);
        mma16(out[0], pa, b0);
        mma16(out[1], pa, b0 + 2);
        mma16(out[2], pa, b1);
        mma16(out[3], pa, b1 + 2);
    }

    const unsigned fm = 0xffffffffu;
    l_lo += __shfl_xor_sync(fm, l_lo, 1);
    l_lo += __shfl_xor_sync(fm, l_lo, 2);
    l_hi += __shfl_xor_sync(fm, l_hi, 1);
    l_hi += __shfl_xor_sync(fm, l_hi, 2);

    const float inv_lo = __frcp_rn(l_lo);
    const float inv_hi = __frcp_rn(l_hi);
    __half* o_lo = g_att + ((size_t)((b * HH + i_lo) * WW + j)) * 128 + h * 32;
    __half* o_hi = g_att + ((size_t)((b * HH + i_hi) * WW + j)) * 128 + h * 32;
#pragma unroll
    for (int nt = 0; nt < 4; nt++) {
        *(__half2*)(o_lo + nt * 8 + 2 * lc) =
            __floats2half2_rn(out[nt][0] * inv_lo, out[nt][1] * inv_lo);
        *(__half2*)(o_hi + nt * 8 + 2 * lc) =
            __floats2half2_rn(out[nt][2] * inv_hi, out[nt][3] * inv_hi);
    }
}

// ---------------------------------------------------------------------------
// Launch
// ---------------------------------------------------------------------------
extern "C" void kernel_launch(void* const* d_in, const int* in_sizes, int n_in,
                              void* d_out, int out_size)
{
    const float* x      = (const float*)d_in[0];  // [4,56,56,128]
    const float* w_qkv  = (const float*)d_in[1];  // [128,384]
    const float* b_qkv  = (const float*)d_in[2];  // [384]
    const float* rpb    = (const float*)d_in[3];  // [4,13,13]
    const float* w_proj = (const float*)d_in[4];  // [128,128]
    const float* b_proj = (const float*)d_in[5];  // [128]
    float* out = (float*)d_out;                   // [4,56,56,128] fp32
    (void)in_sizes; (void)n_in; (void)out_size;

    __half *qkv_buf, *att_buf;
    cudaGetSymbolAddress((void**)&qkv_buf, g_qkv);
    cudaGetSymbolAddress((void**)&att_buf, g_att);

    constexpr int SMQ = (2 * 4 * 128 * 20 + 4 * 2576) * 4;   // ~123 KB
    constexpr int SMP = (2 * 4 * 128 * 20 + 2 * 2576) * 4;   // ~102 KB

    cudaFuncSetAttribute((const void*)gemm_col<128, false, true>,
                         cudaFuncAttributeMaxDynamicSharedMemorySize, SMQ);
    cudaFuncSetAttribute((const void*)gemm_col<64, true, false>,
                         cudaFuncAttributeMaxDynamicSharedMemorySize, SMP);

    // 1) QKV projection: [12544,128] @ [128,384] + b_qkv -> half
    gemm_col<128, false, true><<<dim3(3, 49), 512, SMQ>>>(
        x, w_qkv, b_qkv, qkv_buf, 384);

    // 2) Neighborhood attention (streaming tensor-core flash)
    natten_kernel<<<dim3(49, 4, 4), 128>>>(qkv_buf, rpb);

    // 3) Output projection: [12544,128] @ [128,128] + b_proj -> float
    gemm_col<64, true, false><<<dim3(2, 49), 512, SMP>>>(
        att_buf, w_proj, b_proj, out, 128);
}

// round 15
// speedup vs baseline: 1.0592x; 1.0592x over previous
#include <cuda_runtime.h>
#include <cuda_fp16.h>
#include <cstdint>

#define HH 56
#define WW 56
#define NPIX (4 * 56 * 56)   // 12544

// Scratch (device globals — no allocation allowed). fp16 interchange format.
__device__ __align__(16) __half g_qkv[NPIX * 384];   // [pix][3*128] (q|k|v)
__device__ __align__(16) __half g_att[NPIX * 128];   // attention output

// ---------------------------------------------------------------------------
// helpers
// ---------------------------------------------------------------------------
__device__ __forceinline__ void mma16(float* c, const uint32_t* a, const uint32_t* b) {
    asm volatile(
        "mma.sync.aligned.m16n8k16.row.col.f32.f16.f16.f32 "
        "{%0,%1,%2,%3}, {%4,%5,%6,%7}, {%8,%9}, {%0,%1,%2,%3};"
        : "+f"(c[0]), "+f"(c[1]), "+f"(c[2]), "+f"(c[3])
        : "r"(a[0]), "r"(a[1]), "r"(a[2]), "r"(a[3]), "r"(b[0]), "r"(b[1]));
}
__device__ __forceinline__ void ldm4(uint32_t* r, uint32_t addr) {
    asm volatile("ldmatrix.sync.aligned.m8n8.x4.shared.b16 {%0,%1,%2,%3}, [%4];"
                 : "=r"(r[0]), "=r"(r[1]), "=r"(r[2]), "=r"(r[3]) : "r"(addr));
}
__device__ __forceinline__ void ldm4t(uint32_t* r, uint32_t addr) {
    asm volatile("ldmatrix.sync.aligned.m8n8.x4.trans.shared.b16 {%0,%1,%2,%3}, [%4];"
                 : "=r"(r[0]), "=r"(r[1]), "=r"(r[2]), "=r"(r[3]) : "r"(addr));
}
__device__ __forceinline__ uint32_t h22u(__half2 h) {
    return *reinterpret_cast<uint32_t*>(&h);
}

// ---------------------------------------------------------------------------
// Persistent-column fp16 GEMM + bias (R12 version, unchanged).
// ---------------------------------------------------------------------------
template <int BN, bool AHALF, bool OUTHALF>
__global__ __launch_bounds__(512, 1)
void gemm_col(const void* __restrict__ Av, const float* __restrict__ Wf,
              const float* __restrict__ bias, void* __restrict__ Cv, int N)
{
    constexpr int WN = BN / 4;
    constexpr int NP = (WN + 15) / 16;
    constexpr int NT = WN / 8;
    constexpr int WCS = 2576;
    constexpr int AB = 4 * 128 * 20;

    extern __shared__ uint32_t smg[];
    uint32_t* sA = smg;
    uint32_t* sW = smg + 2 * AB;

    const int t = threadIdx.x, w = t >> 5, lane = t & 31;
    const int wm = w & 3, wn = w >> 2;
    const int lr = lane >> 2, lc = lane & 3;
    const int lt = lane >> 3, rw = lane & 7;
    const int bn = blockIdx.x * BN;
    const int mbase = blockIdx.y * 256;

    {
        constexpr int WU = (128 * (BN / 8)) / 512;
#pragma unroll
        for (int u = 0; u < WU; u++) {
            int g = t + 512 * u;
            int k = g / (BN / 8), ni = g % (BN / 8);
            const float* Wp = Wf + (size_t)k * N + bn + ni * 8;
            float4 f0 = *(const float4*)(Wp);
            float4 f1 = *(const float4*)(Wp + 4);
            uint4 v;
            v.x = h22u(__floats2half2_rn(f0.x, f0.y));
            v.y = h22u(__floats2half2_rn(f0.z, f0.w));
            v.z = h22u(__floats2half2_rn(f1.x, f1.y));
            v.w = h22u(__floats2half2_rn(f1.z, f1.w));
            *(uint4*)(sW + (ni >> 2) * WCS + k * 20 + (ni & 3) * 4) = v;
        }
    }

    const uint32_t smb = (uint32_t)__cvta_generic_to_shared(smg);
    uint32_t aPat[2];
#pragma unroll
    for (int mt = 0; mt < 2; mt++)
        aPat[mt] = ((wm * 32 + mt * 16 + (lt & 1) * 8 + rw) * 20
                    + (lt >> 1) * 4) * 4;
    const uint32_t vpat = ((((lane >> 3) & 1) * 8 + (lane & 7)) * 20
                           + (lane >> 4) * 4) * 4;
    uint32_t bAddr[NP];
#pragma unroll
    for (int p = 0; p < NP; p++) {
        int n0 = wn * WN + p * 16;
        bAddr[p] = smb + (2 * AB + (n0 >> 5) * WCS) * 4 + vpat
                   + ((n0 & 16) ? 32 : 0);
    }
    float bs0[NT], bs1[NT];
#pragma unroll
    for (int nt = 0; nt < NT; nt++) {
        int c = bn + wn * WN + nt * 8 + lc * 2;
        bs0[nt] = bias[c];
        bs1[nt] = bias[c + 1];
    }

    const int arow = t >> 2, aseg = t & 3;
    float4 aF[8];
    uint4 aH[4];

    auto ldg_tile = [&](int m) {
        if constexpr (!AHALF) {
            const float* Ap = (const float*)Av
                + (size_t)(mbase + m * 128 + arow) * 128 + aseg * 8;
#pragma unroll
            for (int s = 0; s < 4; s++) {
                aF[2 * s]     = *(const float4*)(Ap + s * 32);
                aF[2 * s + 1] = *(const float4*)(Ap + s * 32 + 4);
            }
        } else {
            const __half* Ap = (const __half*)Av
                + (size_t)(mbase + m * 128 + arow) * 128 + aseg * 8;
#pragma unroll
            for (int s = 0; s < 4; s++)
                aH[s] = *(const uint4*)(Ap + s * 32);
        }
    };
    auto sts_tile = [&](int m) {
        uint32_t* dst = sA + (m & 1) * AB + arow * 20 + aseg * 4;
        if constexpr (!AHALF) {
#pragma unroll
            for (int s = 0; s < 4; s++) {
                uint4 v;
                v.x = h22u(__floats2half2_rn(aF[2 * s].x, aF[2 * s].y));
                v.y = h22u(__floats2half2_rn(aF[2 * s].z, aF[2 * s].w));
                v.z = h22u(__floats2half2_rn(aF[2 * s + 1].x, aF[2 * s + 1].y));
                v.w = h22u(__floats2half2_rn(aF[2 * s + 1].z, aF[2 * s + 1].w));
                *(uint4*)(dst + s * 2560) = v;
            }
        } else {
#pragma unroll
            for (int s = 0; s < 4; s++)
                *(uint4*)(dst + s * 2560) = aH[s];
        }
    };

    ldg_tile(0);

#pragma unroll 1
    for (int m = 0; m < 2; m++) {
        sts_tile(m);
        __syncthreads();
        if (m < 1) ldg_tile(m + 1);

        float acc[2][NT][4];
#pragma unroll
        for (int mt = 0; mt < 2; mt++)
#pragma unroll
            for (int nt = 0; nt < NT; nt++)
#pragma unroll
                for (int i = 0; i < 4; i++) acc[mt][nt][i] = 0.f;

        const uint32_t aBase = smb + (m & 1) * AB * 4;
#pragma unroll
        for (int s = 0; s < 8; s++) {
            uint32_t af[2][4], bf[NT][2];
            ldm4(af[0], aBase + aPat[0] + (s >> 1) * 10240 + (s & 1) * 32);
            ldm4(af[1], aBase + aPat[1] + (s >> 1) * 10240 + (s & 1) * 32);
#pragma unroll
            for (int p = 0; p < NP; p++) {
                uint32_t r4[4];
                ldm4t(r4, bAddr[p] + s * 1280);
                bf[2 * p][0] = r4[0]; bf[2 * p][1] = r4[1];
                bf[2 * p + 1][0] = r4[2]; bf[2 * p + 1][1] = r4[3];
            }
#pragma unroll
            for (int mt = 0; mt < 2; mt++)
#pragma unroll
                for (int nt = 0; nt < NT; nt++)
                    mma16(acc[mt][nt], af[mt], bf[nt]);
        }

#pragma unroll
        for (int mt = 0; mt < 2; mt++) {
            const int r0 = mbase + m * 128 + wm * 32 + mt * 16 + lr;
#pragma unroll
            for (int nt = 0; nt < NT; nt++) {
                int c = bn + wn * WN + nt * 8 + lc * 2;
                if constexpr (OUTHALF) {
                    __half* Ch = (__half*)Cv;
                    *(__half2*)(Ch + (size_t)r0 * N + c) =
                        __floats2half2_rn(acc[mt][nt][0] + bs0[nt],
                                          acc[mt][nt][1] + bs1[nt]);
                    *(__half2*)(Ch + (size_t)(r0 + 8) * N + c) =
                        __floats2half2_rn(acc[mt][nt][2] + bs0[nt],
                                          acc[mt][nt][3] + bs1[nt]);
                } else {
                    float* Cf = (float*)Cv;
                    *(float2*)(Cf + (size_t)r0 * N + c) =
                        make_float2(acc[mt][nt][0] + bs0[nt],
                                    acc[mt][nt][1] + bs1[nt]);
                    *(float2*)(Cf + (size_t)(r0 + 8) * N + c) =
                        make_float2(acc[mt][nt][2] + bs0[nt],
                                    acc[mt][nt][3] + bs1[nt]);
                }
            }
        }
    }
}

// ---------------------------------------------------------------------------
// Streaming flash natten v2 (R13 architecture, pad-zero indexing FIXED):
// padded 16-key rows (kr = t2, kc hoisted), 256 threads = 8 warps
// (qw = query rows, kh = key-tile parity). Partials combined via smem
// staging aliased onto the dead K region.
// ---------------------------------------------------------------------------
#define SQ_OFF 0
#define SK_OFF (64 * 20)                 // 1280
#define SV_OFF (SK_OFF + 224 * 20)       // 5760
#define SM_WORDS (SV_OFF + 224 * 20)     // 10240 words = 40 KB

__global__ __launch_bounds__(256)
void natten_kernel(const __half* __restrict__ qkv, const float* __restrict__ rpb)
{
    __shared__ __align__(16) uint32_t sm[SM_WORDS];
    __shared__ float rp[169];

    const int tile = blockIdx.x;             // 0..48
    const int ti = tile / 7, tj = tile % 7;
    const int h = blockIdx.y, b = blockIdx.z;
    const int i0 = ti * 8, j0 = tj * 8;
    const int r0 = min(max(i0 - 3, 0), HH - 14);
    const int c0 = min(max(j0 - 3, 0), WW - 14);
    const int tid = threadIdx.x;

    for (int e = tid; e < 169; e += 256) rp[e] = rpb[h * 169 + e];

    // Q: 64 rows x 32 halves (one uint4 per thread)
    {
        int row = tid >> 2, seg = tid & 3;
        int qi = row >> 3, qj = row & 7;
        size_t pix = (size_t)((b * HH + i0 + qi) * WW + j0 + qj);
        *(uint4*)(sm + SQ_OFF + row * 20 + seg * 4) =
            *(const uint4*)(qkv + pix * 384 + h * 32 + seg * 8);
    }
    // K and V: 196 real window rows into padded [r*16+c] positions
    for (int e = tid; e < 784; e += 256) {
        int pos = e >> 2, seg = e & 3;
        int r = pos / 14, c = pos - r * 14;
        size_t pix = (size_t)((b * HH + r0 + r) * WW + c0 + c);
        const __half* base = qkv + pix * 384 + h * 32;
        int off = (r * 16 + c) * 20 + seg * 4;
        *(uint4*)(sm + SK_OFF + off) = *(const uint4*)(base + 128 + seg * 8);
        *(uint4*)(sm + SV_OFF + off) = *(const uint4*)(base + 256 + seg * 8);
    }
    // zero pad columns c = 14,15 of each of 14 rows (16 data words per pos).
    // FIXED indexing: iterate the 448 pad words directly, zero K and V both.
    for (int e = tid; e < 448; e += 256) {
        int p = e >> 4, wd = e & 15;
        int off = ((p >> 1) * 16 + 14 + (p & 1)) * 20 + wd;
        sm[SK_OFF + off] = 0;
        sm[SV_OFF + off] = 0;
    }
    __syncthreads();

    const int w = tid >> 5, lane = tid & 31;
    const int qw = w & 3, kh = w >> 2;
    const int lr = lane >> 2, lc = lane & 3;
    const int lt = lane >> 3, rw = lane & 7;

    const uint32_t base = (uint32_t)__cvta_generic_to_shared(sm);
    const uint32_t aAddr = base + SQ_OFF * 4
        + ((qw * 16 + (lt & 1) * 8 + rw) * 20 + ((lt >> 1) << 2)) * 4;
    const uint32_t kAddr = base + SK_OFF * 4
        + ((((lt >> 1) << 3) + rw) * 20 + ((lt & 1) << 2)) * 4;
    const uint32_t vAddr = base + SV_OFF * 4
        + (((((lane >> 3) & 1) << 3) + (lane & 7)) * 20 + ((lane >> 4) << 2)) * 4;

    uint32_t af0[4], af1[4];
    ldm4(af0, aAddr);
    ldm4(af1, aAddr + 32);

    const int i_lo = i0 + 2 * qw, i_hi = i_lo + 1;
    const int j = j0 + lr;
    const int kri_lo = min(max(i_lo - 3, 0), HH - 7) - r0;
    const int kri_hi = min(max(i_hi - 3, 0), HH - 7) - r0;
    const int kcj = min(max(j - 3, 0), WW - 7) - c0;
    const int ci_lo = 6 - (i_lo - r0);
    const int ci_hi = 6 - (i_hi - r0);
    const int cj = 6 - (j - c0);
    const float scale = 0.17677669529663687f;   // 32^-0.5

    // hoisted per-key-column constants (kc fixed per (tt,c))
    bool vC[2][2];
    int  cb[2][2];
#pragma unroll
    for (int tt = 0; tt < 2; tt++)
#pragma unroll
        for (int c = 0; c < 2; c++) {
            int kc = tt * 8 + 2 * lc + c;
            vC[tt][c] = (unsigned)(kc - kcj) < 7u;
            cb[tt][c] = kc + cj;
        }

    float out[4][4];
#pragma unroll
    for (int nt = 0; nt < 4; nt++)
#pragma unroll
        for (int i = 0; i < 4; i++) out[nt][i] = 0.f;
    float l_lo = 0.f, l_hi = 0.f;

#pragma unroll
    for (int step = 0; step < 7; step++) {
        const int t2 = 2 * step + kh;            // kr == t2 (padded rows)
        const uint32_t aoff = (uint32_t)t2 * 1280;

        float sacc[2][4];
#pragma unroll
        for (int tt = 0; tt < 2; tt++)
#pragma unroll
            for (int i = 0; i < 4; i++) sacc[tt][i] = 0.f;
        {
            uint32_t r4[4];
            ldm4(r4, kAddr + aoff);
            mma16(sacc[0], af0, r4);
            mma16(sacc[1], af0, r4 + 2);
            ldm4(r4, kAddr + aoff + 32);
            mma16(sacc[0], af1, r4);
            mma16(sacc[1], af1, r4 + 2);
        }

        const bool rok_lo = (unsigned)(t2 - kri_lo) < 7u;
        const bool rok_hi = (unsigned)(t2 - kri_hi) < 7u;
        const int rb_lo = (t2 + ci_lo) * 13;
        const int rb_hi = (t2 + ci_hi) * 13;

        uint32_t pa[4];
#pragma unroll
        for (int tt = 0; tt < 2; tt++) {
#pragma unroll
            for (int c = 0; c < 2; c++) {
                bool ok1 = rok_lo && vC[tt][c];
                int idx1 = min(max(rb_lo + cb[tt][c], 0), 168);
                float e1 = __expf(ok1 ? fmaf(sacc[tt][c], scale, rp[idx1]) : -60.f);
                sacc[tt][c] = e1;
                l_lo += e1;

                bool ok2 = rok_hi && vC[tt][c];
                int idx2 = min(max(rb_hi + cb[tt][c], 0), 168);
                float e2 = __expf(ok2 ? fmaf(sacc[tt][2 + c], scale, rp[idx2]) : -60.f);
                sacc[tt][2 + c] = e2;
                l_hi += e2;
            }
        }
        pa[0] = h22u(__floats2half2_rn(sacc[0][0], sacc[0][1]));
        pa[1] = h22u(__floats2half2_rn(sacc[0][2], sacc[0][3]));
        pa[2] = h22u(__floats2half2_rn(sacc[1][0], sacc[1][1]));
        pa[3] = h22u(__floats2half2_rn(sacc[1][2], sacc[1][3]));

        uint32_t b0[4], b1[4];
        ldm4t(b0, vAddr + aoff);
        ldm4t(b1, vAddr + aoff + 32);
        mma16(out[0], pa, b0);
        mma16(out[1], pa, b0 + 2);
        mma16(out[2], pa, b1);
        mma16(out[3], pa, b1 + 2);
    }

    // ---- cross-warp combine (kh=1 -> staging -> kh=0 adds) ----
    __syncthreads();                       // K region dead; reuse as staging
    float* stg = (float*)(sm + SK_OFF);
    const int sl = (qw * 32 + lane) * 19;
    if (kh == 1) {
#pragma unroll
        for (int nt = 0; nt < 4; nt++)
#pragma unroll
            for (int i = 0; i < 4; i++) stg[sl + nt * 4 + i] = out[nt][i];
        stg[sl + 16] = l_lo;
        stg[sl + 17] = l_hi;
    }
    __syncthreads();

    if (kh == 0) {
#pragma unroll
        for (int nt = 0; nt < 4; nt++)
#pragma unroll
            for (int i = 0; i < 4; i++) out[nt][i] += stg[sl + nt * 4 + i];
        l_lo += stg[sl + 16];
        l_hi += stg[sl + 17];

        const unsigned fm = 0xffffffffu;
        l_lo += __shfl_xor_sync(fm, l_lo, 1);
        l_lo += __shfl_xor_sync(fm, l_lo, 2);
        l_hi += __shfl_xor_sync(fm, l_hi, 1);
        l_hi += __shfl_xor_sync(fm, l_hi, 2);

        const float inv_lo = __frcp_rn(l_lo);
        const float inv_hi = __frcp_rn(l_hi);
        __half* o_lo = g_att + ((size_t)((b * HH + i_lo) * WW + j)) * 128 + h * 32;
        __half* o_hi = g_att + ((size_t)((b * HH + i_hi) * WW + j)) * 128 + h * 32;
#pragma unroll
        for (int nt = 0; nt < 4; nt++) {
            *(__half2*)(o_lo + nt * 8 + 2 * lc) =
                __floats2half2_rn(out[nt][0] * inv_lo, out[nt][1] * inv_lo);
            *(__half2*)(o_hi + nt * 8 + 2 * lc) =
                __floats2half2_rn(out[nt][2] * inv_hi, out[nt][3] * inv_hi);
        }
    }
}

// ---------------------------------------------------------------------------
// Launch
// ---------------------------------------------------------------------------
extern "C" void kernel_launch(void* const* d_in, const int* in_sizes, int n_in,
                              void* d_out, int out_size)
{
    const float* x      = (const float*)d_in[0];  // [4,56,56,128]
    const float* w_qkv  = (const float*)d_in[1];  // [128,384]
    const float* b_qkv  = (const float*)d_in[2];  // [384]
    const float* rpb    = (const float*)d_in[3];  // [4,13,13]
    const float* w_proj = (const float*)d_in[4];  // [128,128]
    const float* b_proj = (const float*)d_in[5];  // [128]
    float* out = (float*)d_out;                   // [4,56,56,128] fp32
    (void)in_sizes; (void)n_in; (void)out_size;

    __half *qkv_buf, *att_buf;
    cudaGetSymbolAddress((void**)&qkv_buf, g_qkv);
    cudaGetSymbolAddress((void**)&att_buf, g_att);

    constexpr int SMQ = (2 * 4 * 128 * 20 + 4 * 2576) * 4;   // ~123 KB
    constexpr int SMP = (2 * 4 * 128 * 20 + 2 * 2576) * 4;   // ~102 KB

    cudaFuncSetAttribute((const void*)gemm_col<128, false, true>,
                         cudaFuncAttributeMaxDynamicSharedMemorySize, SMQ);
    cudaFuncSetAttribute((const void*)gemm_col<64, true, false>,
                         cudaFuncAttributeMaxDynamicSharedMemorySize, SMP);

    // 1) QKV projection: [12544,128] @ [128,384] + b_qkv -> half
    gemm_col<128, false, true><<<dim3(3, 49), 512, SMQ>>>(
        x, w_qkv, b_qkv, qkv_buf, 384);

    // 2) Neighborhood attention (padded rows + split key tiles, 8 warps)
    natten_kernel<<<dim3(49, 4, 4), 256>>>(qkv_buf, rpb);

    // 3) Output projection: [12544,128] @ [128,128] + b_proj -> float
    gemm_col<64, true, false><<<dim3(2, 49), 512, SMP>>>(
        att_buf, w_proj, b_proj, out, 128);
}

// round 16
// speedup vs baseline: 1.0673x; 1.0077x over previous
#include <cuda_runtime.h>
#include <cuda_fp16.h>
#include <cstdint>

#define HH 56
#define WW 56
#define NPIX (4 * 56 * 56)   // 12544

// Scratch (device globals — no allocation allowed). fp16 interchange format.
__device__ __align__(16) __half g_qkv[NPIX * 384];   // [pix][3*128] (q|k|v)
__device__ __align__(16) __half g_att[NPIX * 128];   // attention output

// ---------------------------------------------------------------------------
// helpers
// ---------------------------------------------------------------------------
__device__ __forceinline__ void mma16(float* c, const uint32_t* a, const uint32_t* b) {
    asm volatile(
        "mma.sync.aligned.m16n8k16.row.col.f32.f16.f16.f32 "
        "{%0,%1,%2,%3}, {%4,%5,%6,%7}, {%8,%9}, {%0,%1,%2,%3};"
        : "+f"(c[0]), "+f"(c[1]), "+f"(c[2]), "+f"(c[3])
        : "r"(a[0]), "r"(a[1]), "r"(a[2]), "r"(a[3]), "r"(b[0]), "r"(b[1]));
}
__device__ __forceinline__ void ldm4(uint32_t* r, uint32_t addr) {
    asm volatile("ldmatrix.sync.aligned.m8n8.x4.shared.b16 {%0,%1,%2,%3}, [%4];"
                 : "=r"(r[0]), "=r"(r[1]), "=r"(r[2]), "=r"(r[3]) : "r"(addr));
}
__device__ __forceinline__ void ldm4t(uint32_t* r, uint32_t addr) {
    asm volatile("ldmatrix.sync.aligned.m8n8.x4.trans.shared.b16 {%0,%1,%2,%3}, [%4];"
                 : "=r"(r[0]), "=r"(r[1]), "=r"(r[2]), "=r"(r[3]) : "r"(addr));
}
__device__ __forceinline__ uint32_t h22u(__half2 h) {
    return *reinterpret_cast<uint32_t*>(&h);
}

// ---------------------------------------------------------------------------
// Persistent-column fp16 GEMM + bias, 256 threads, ONE 128-row m-tile per
// block, multi-block-per-SM residency (the latency-overlap axis):
//   C[M,N] = A[M,128] @ W[k=128][N] + bias
// Grid (N/BN, 98). 8 warps as 4m x 2n, MT=2 (warp = 32 rows x BN/2 cols).
// All fragment/addressing patterns identical to the R12-validated versions.
// smem: 1 A buffer (40 KB) + W column -> 82 KB (BN=128) / 61.6 KB (BN=64).
// ---------------------------------------------------------------------------
template <int BN, bool AHALF, bool OUTHALF, int MAXB>
__global__ __launch_bounds__(256, MAXB)
void gemm_col(const void* __restrict__ Av, const float* __restrict__ Wf,
              const float* __restrict__ bias, void* __restrict__ Cv, int N)
{
    constexpr int WN = BN / 2;                 // n cols per warp (64 or 32)
    constexpr int NP = WN / 16;                // n16 ldmatrix tiles per warp
    constexpr int NT = WN / 8;                 // mma n tiles per warp
    constexpr int WCS = 2576;                  // W chunk stride (words)
    constexpr int AB = 4 * 128 * 20;           // A words (4 k-chunks), 1 buffer

    extern __shared__ uint32_t smg[];
    uint32_t* sA = smg;
    uint32_t* sW = smg + AB;

    const int t = threadIdx.x, w = t >> 5, lane = t & 31;
    const int wm = w & 3, wn = w >> 2;
    const int lr = lane >> 2, lc = lane & 3;
    const int lt = lane >> 3, rw = lane & 7;
    const int bn = blockIdx.x * BN;
    const int mbase = blockIdx.y * 128;        // one 128-row tile

    // ---- stage W: [k][n] -> chunked halves (f32->f16 on the fly) ----
    {
        constexpr int WU = (128 * (BN / 8)) / 256;
#pragma unroll
        for (int u = 0; u < WU; u++) {
            int g = t + 256 * u;
            int k = g / (BN / 8), ni = g % (BN / 8);
            const float* Wp = Wf + (size_t)k * N + bn + ni * 8;
            float4 f0 = *(const float4*)(Wp);
            float4 f1 = *(const float4*)(Wp + 4);
            uint4 v;
            v.x = h22u(__floats2half2_rn(f0.x, f0.y));
            v.y = h22u(__floats2half2_rn(f0.z, f0.w));
            v.z = h22u(__floats2half2_rn(f1.x, f1.y));
            v.w = h22u(__floats2half2_rn(f1.z, f1.w));
            *(uint4*)(sW + (ni >> 2) * WCS + k * 20 + (ni & 3) * 4) = v;
        }
    }
    // ---- stage A: 128 rows x 128 halves, chunked stride-20 layout ----
#pragma unroll
    for (int u = 0; u < 8; u++) {
        int g = t + 256 * u;
        int s = g >> 9, rem = g & 511;
        int row = rem >> 2, seg = rem & 3;
        uint32_t* dst = sA + s * 2560 + row * 20 + seg * 4;
        if constexpr (!AHALF) {
            const float* Ap = (const float*)Av
                + (size_t)(mbase + row) * 128 + s * 32 + seg * 8;
            float4 f0 = *(const float4*)(Ap);
            float4 f1 = *(const float4*)(Ap + 4);
            uint4 v;
            v.x = h22u(__floats2half2_rn(f0.x, f0.y));
            v.y = h22u(__floats2half2_rn(f0.z, f0.w));
            v.z = h22u(__floats2half2_rn(f1.x, f1.y));
            v.w = h22u(__floats2half2_rn(f1.z, f1.w));
            *(uint4*)dst = v;
        } else {
            const __half* Ap = (const __half*)Av
                + (size_t)(mbase + row) * 128 + s * 32 + seg * 8;
            *(uint4*)dst = *(const uint4*)(Ap);
        }
    }
    __syncthreads();

    // ---- fragment addresses (R12-validated patterns) ----
    const uint32_t smb = (uint32_t)__cvta_generic_to_shared(smg);
    uint32_t aPat[2];
#pragma unroll
    for (int mt = 0; mt < 2; mt++)
        aPat[mt] = ((wm * 32 + mt * 16 + (lt & 1) * 8 + rw) * 20
                    + (lt >> 1) * 4) * 4;
    const uint32_t vpat = ((((lane >> 3) & 1) * 8 + (lane & 7)) * 20
                           + (lane >> 4) * 4) * 4;
    uint32_t bAddr[NP];
#pragma unroll
    for (int p = 0; p < NP; p++) {
        int n0 = wn * WN + p * 16;
        bAddr[p] = smb + (AB + (n0 >> 5) * WCS) * 4 + vpat
                   + ((n0 & 16) ? 32 : 0);
    }
    float bs0[NT], bs1[NT];
#pragma unroll
    for (int nt = 0; nt < NT; nt++) {
        int c = bn + wn * WN + nt * 8 + lc * 2;
        bs0[nt] = bias[c];
        bs1[nt] = bias[c + 1];
    }

    // ---- mainloop: 8 k-steps, sync-free ----
    float acc[2][NT][4];
#pragma unroll
    for (int mt = 0; mt < 2; mt++)
#pragma unroll
        for (int nt = 0; nt < NT; nt++)
#pragma unroll
            for (int i = 0; i < 4; i++) acc[mt][nt][i] = 0.f;

#pragma unroll
    for (int s = 0; s < 8; s++) {
        uint32_t af[2][4], bf[NT][2];
        ldm4(af[0], smb + aPat[0] + (s >> 1) * 10240 + (s & 1) * 32);
        ldm4(af[1], smb + aPat[1] + (s >> 1) * 10240 + (s & 1) * 32);
#pragma unroll
        for (int p = 0; p < NP; p++) {
            uint32_t r4[4];
            ldm4t(r4, bAddr[p] + s * 1280);
            bf[2 * p][0] = r4[0]; bf[2 * p][1] = r4[1];
            bf[2 * p + 1][0] = r4[2]; bf[2 * p + 1][1] = r4[3];
        }
#pragma unroll
        for (int mt = 0; mt < 2; mt++)
#pragma unroll
            for (int nt = 0; nt < NT; nt++)
                mma16(acc[mt][nt], af[mt], bf[nt]);
    }

    // ---- epilogue with bias ----
#pragma unroll
    for (int mt = 0; mt < 2; mt++) {
        const int r0 = mbase + wm * 32 + mt * 16 + lr;
#pragma unroll
        for (int nt = 0; nt < NT; nt++) {
            int c = bn + wn * WN + nt * 8 + lc * 2;
            if constexpr (OUTHALF) {
                __half* Ch = (__half*)Cv;
                *(__half2*)(Ch + (size_t)r0 * N + c) =
                    __floats2half2_rn(acc[mt][nt][0] + bs0[nt],
                                      acc[mt][nt][1] + bs1[nt]);
                *(__half2*)(Ch + (size_t)(r0 + 8) * N + c) =
                    __floats2half2_rn(acc[mt][nt][2] + bs0[nt],
                                      acc[mt][nt][3] + bs1[nt]);
            } else {
                float* Cf = (float*)Cv;
                *(float2*)(Cf + (size_t)r0 * N + c) =
                    make_float2(acc[mt][nt][0] + bs0[nt],
                                acc[mt][nt][1] + bs1[nt]);
                *(float2*)(Cf + (size_t)(r0 + 8) * N + c) =
                    make_float2(acc[mt][nt][2] + bs0[nt],
                                acc[mt][nt][3] + bs1[nt]);
            }
        }
    }
}

// ---------------------------------------------------------------------------
// Streaming flash natten (R14-validated, verbatim): padded 16-key rows
// (kr = t2, kc hoisted), 256 threads = 8 warps (qw query rows, kh key
// parity), partials combined via smem staging on the dead K region.
// ---------------------------------------------------------------------------
#define SQ_OFF 0
#define SK_OFF (64 * 20)                 // 1280
#define SV_OFF (SK_OFF + 224 * 20)       // 5760
#define SM_WORDS (SV_OFF + 224 * 20)     // 10240 words = 40 KB

__global__ __launch_bounds__(256)
void natten_kernel(const __half* __restrict__ qkv, const float* __restrict__ rpb)
{
    __shared__ __align__(16) uint32_t sm[SM_WORDS];
    __shared__ float rp[169];

    const int tile = blockIdx.x;             // 0..48
    const int ti = tile / 7, tj = tile % 7;
    const int h = blockIdx.y, b = blockIdx.z;
    const int i0 = ti * 8, j0 = tj * 8;
    const int r0 = min(max(i0 - 3, 0), HH - 14);
    const int c0 = min(max(j0 - 3, 0), WW - 14);
    const int tid = threadIdx.x;

    for (int e = tid; e < 169; e += 256) rp[e] = rpb[h * 169 + e];

    // Q: 64 rows x 32 halves (one uint4 per thread)
    {
        int row = tid >> 2, seg = tid & 3;
        int qi = row >> 3, qj = row & 7;
        size_t pix = (size_t)((b * HH + i0 + qi) * WW + j0 + qj);
        *(uint4*)(sm + SQ_OFF + row * 20 + seg * 4) =
            *(const uint4*)(qkv + pix * 384 + h * 32 + seg * 8);
    }
    // K and V: 196 real window rows into padded [r*16+c] positions
    for (int e = tid; e < 784; e += 256) {
        int pos = e >> 2, seg = e & 3;
        int r = pos / 14, c = pos - r * 14;
        size_t pix = (size_t)((b * HH + r0 + r) * WW + c0 + c);
        const __half* base = qkv + pix * 384 + h * 32;
        int off = (r * 16 + c) * 20 + seg * 4;
        *(uint4*)(sm + SK_OFF + off) = *(const uint4*)(base + 128 + seg * 8);
        *(uint4*)(sm + SV_OFF + off) = *(const uint4*)(base + 256 + seg * 8);
    }
    // zero pad columns c = 14,15 of each of 14 rows (448 words each tensor)
    for (int e = tid; e < 448; e += 256) {
        int p = e >> 4, wd = e & 15;
        int off = ((p >> 1) * 16 + 14 + (p & 1)) * 20 + wd;
        sm[SK_OFF + off] = 0;
        sm[SV_OFF + off] = 0;
    }
    __syncthreads();

    const int w = tid >> 5, lane = tid & 31;
    const int qw = w & 3, kh = w >> 2;
    const int lr = lane >> 2, lc = lane & 3;
    const int lt = lane >> 3, rw = lane & 7;

    const uint32_t base = (uint32_t)__cvta_generic_to_shared(sm);
    const uint32_t aAddr = base + SQ_OFF * 4
        + ((qw * 16 + (lt & 1) * 8 + rw) * 20 + ((lt >> 1) << 2)) * 4;
    const uint32_t kAddr = base + SK_OFF * 4
        + ((((lt >> 1) << 3) + rw) * 20 + ((lt & 1) << 2)) * 4;
    const uint32_t vAddr = base + SV_OFF * 4
        + (((((lane >> 3) & 1) << 3) + (lane & 7)) * 20 + ((lane >> 4) << 2)) * 4;

    uint32_t af0[4], af1[4];
    ldm4(af0, aAddr);
    ldm4(af1, aAddr + 32);

    const int i_lo = i0 + 2 * qw, i_hi = i_lo + 1;
    const int j = j0 + lr;
    const int kri_lo = min(max(i_lo - 3, 0), HH - 7) - r0;
    const int kri_hi = min(max(i_hi - 3, 0), HH - 7) - r0;
    const int kcj = min(max(j - 3, 0), WW - 7) - c0;
    const int ci_lo = 6 - (i_lo - r0);
    const int ci_hi = 6 - (i_hi - r0);
    const int cj = 6 - (j - c0);
    const float scale = 0.17677669529663687f;   // 32^-0.5

    // hoisted per-key-column constants (kc fixed per (tt,c))
    bool vC[2][2];
    int  cb[2][2];
#pragma unroll
    for (int tt = 0; tt < 2; tt++)
#pragma unroll
        for (int c = 0; c < 2; c++) {
            int kc = tt * 8 + 2 * lc + c;
            vC[tt][c] = (unsigned)(kc - kcj) < 7u;
            cb[tt][c] = kc + cj;
        }

    float out[4][4];
#pragma unroll
    for (int nt = 0; nt < 4; nt++)
#pragma unroll
        for (int i = 0; i < 4; i++) out[nt][i] = 0.f;
    float l_lo = 0.f, l_hi = 0.f;

#pragma unroll
    for (int step = 0; step < 7; step++) {
        const int t2 = 2 * step + kh;            // kr == t2 (padded rows)
        const uint32_t aoff = (uint32_t)t2 * 1280;

        float sacc[2][4];
#pragma unroll
        for (int tt = 0; tt < 2; tt++)
#pragma unroll
            for (int i = 0; i < 4; i++) sacc[tt][i] = 0.f;
        {
            uint32_t r4[4];
            ldm4(r4, kAddr + aoff);
            mma16(sacc[0], af0, r4);
            mma16(sacc[1], af0, r4 + 2);
            ldm4(r4, kAddr + aoff + 32);
            mma16(sacc[0], af1, r4);
            mma16(sacc[1], af1, r4 + 2);
        }

        const bool rok_lo = (unsigned)(t2 - kri_lo) < 7u;
        const bool rok_hi = (unsigned)(t2 - kri_hi) < 7u;
        const int rb_lo = (t2 + ci_lo) * 13;
        const int rb_hi = (t2 + ci_hi) * 13;

        uint32_t pa[4];
#pragma unroll
        for (int tt = 0; tt < 2; tt++) {
#pragma unroll
            for (int c = 0; c < 2; c++) {
                bool ok1 = rok_lo && vC[tt][c];
                int idx1 = min(max(rb_lo + cb[tt][c], 0), 168);
                float e1 = __expf(ok1 ? fmaf(sacc[tt][c], scale, rp[idx1]) : -60.f);
                sacc[tt][c] = e1;
                l_lo += e1;

                bool ok2 = rok_hi && vC[tt][c];
                int idx2 = min(max(rb_hi + cb[tt][c], 0), 168);
                float e2 = __expf(ok2 ? fmaf(sacc[tt][2 + c], scale, rp[idx2]) : -60.f);
                sacc[tt][2 + c] = e2;
                l_hi += e2;
            }
        }
        pa[0] = h22u(__floats2half2_rn(sacc[0][0], sacc[0][1]));
        pa[1] = h22u(__floats2half2_rn(sacc[0][2], sacc[0][3]));
        pa[2] = h22u(__floats2half2_rn(sacc[1][0], sacc[1][1]));
        pa[3] = h22u(__floats2half2_rn(sacc[1][2], sacc[1][3]));

        uint32_t b0[4], b1[4];
        ldm4t(b0, vAddr + aoff);
        ldm4t(b1, vAddr + aoff + 32);
        mma16(out[0], pa, b0);
        mma16(out[1], pa, b0 + 2);
        mma16(out[2], pa, b1);
        mma16(out[3], pa, b1 + 2);
    }

    // ---- cross-warp combine (kh=1 -> staging -> kh=0 adds) ----
    __syncthreads();                       // K region dead; reuse as staging
    float* stg = (float*)(sm + SK_OFF);
    const int sl = (qw * 32 + lane) * 19;
    if (kh == 1) {
#pragma unroll
        for (int nt = 0; nt < 4; nt++)
#pragma unroll
            for (int i = 0; i < 4; i++) stg[sl + nt * 4 + i] = out[nt][i];
        stg[sl + 16] = l_lo;
        stg[sl + 17] = l_hi;
    }
    __syncthreads();

    if (kh == 0) {
#pragma unroll
        for (int nt = 0; nt < 4; nt++)
#pragma unroll
            for (int i = 0; i < 4; i++) out[nt][i] += stg[sl + nt * 4 + i];
        l_lo += stg[sl + 16];
        l_hi += stg[sl + 17];

        const unsigned fm = 0xffffffffu;
        l_lo += __shfl_xor_sync(fm, l_lo, 1);
        l_lo += __shfl_xor_sync(fm, l_lo, 2);
        l_hi += __shfl_xor_sync(fm, l_hi, 1);
        l_hi += __shfl_xor_sync(fm, l_hi, 2);

        const float inv_lo = __frcp_rn(l_lo);
        const float inv_hi = __frcp_rn(l_hi);
        __half* o_lo = g_att + ((size_t)((b * HH + i_lo) * WW + j)) * 128 + h * 32;
        __half* o_hi = g_att + ((size_t)((b * HH + i_hi) * WW + j)) * 128 + h * 32;
#pragma unroll
        for (int nt = 0; nt < 4; nt++) {
            *(__half2*)(o_lo + nt * 8 + 2 * lc) =
                __floats2half2_rn(out[nt][0] * inv_lo, out[nt][1] * inv_lo);
            *(__half2*)(o_hi + nt * 8 + 2 * lc) =
                __floats2half2_rn(out[nt][2] * inv_hi, out[nt][3] * inv_hi);
        }
    }
}

// ---------------------------------------------------------------------------
// Launch
// ---------------------------------------------------------------------------
extern "C" void kernel_launch(void* const* d_in, const int* in_sizes, int n_in,
                              void* d_out, int out_size)
{
    const float* x      = (const float*)d_in[0];  // [4,56,56,128]
    const float* w_qkv  = (const float*)d_in[1];  // [128,384]
    const float* b_qkv  = (const float*)d_in[2];  // [384]
    const float* rpb    = (const float*)d_in[3];  // [4,13,13]
    const float* w_proj = (const float*)d_in[4];  // [128,128]
    const float* b_proj = (const float*)d_in[5];  // [128]
    float* out = (float*)d_out;                   // [4,56,56,128] fp32
    (void)in_sizes; (void)n_in; (void)out_size;

    __half *qkv_buf, *att_buf;
    cudaGetSymbolAddress((void**)&qkv_buf, g_qkv);
    cudaGetSymbolAddress((void**)&att_buf, g_att);

    constexpr int SMQ = (4 * 128 * 20 + 4 * 2576) * 4;   // 82176 B
    constexpr int SMP = (4 * 128 * 20 + 2 * 2576) * 4;   // 61568 B

    cudaFuncSetAttribute((const void*)gemm_col<128, false, true, 2>,
                         cudaFuncAttributeMaxDynamicSharedMemorySize, SMQ);
    cudaFuncSetAttribute((const void*)gemm_col<64, true, false, 3>,
                         cudaFuncAttributeMaxDynamicSharedMemorySize, SMP);

    // 1) QKV projection: [12544,128] @ [128,384] + b_qkv -> half
    gemm_col<128, false, true, 2><<<dim3(3, 98), 256, SMQ>>>(
        x, w_qkv, b_qkv, qkv_buf, 384);

    // 2) Neighborhood attention (padded rows + split key tiles, 8 warps)
    natten_kernel<<<dim3(49, 4, 4), 256>>>(qkv_buf, rpb);

    // 3) Output projection: [12544,128] @ [128,128] + b_proj -> float
    gemm_col<64, true, false, 3><<<dim3(2, 98), 256, SMP>>>(
        att_buf, w_proj, b_proj, out, 128);
}

// round 17
// speedup vs baseline: 1.1246x; 1.0537x over previous
#include <cuda_runtime.h>
#include <cuda_fp16.h>
#include <cstdint>

#define HH 56
#define WW 56
#define NPIX (4 * 56 * 56)   // 12544

// Scratch (device globals — no allocation allowed). fp16 interchange format.
__device__ __align__(16) __half g_qkv[NPIX * 384];   // [pix][3*128] (q|k|v)
__device__ __align__(16) __half g_att[NPIX * 128];   // attention output

// ---------------------------------------------------------------------------
// helpers
// ---------------------------------------------------------------------------
__device__ __forceinline__ void mma16(float* c, const uint32_t* a, const uint32_t* b) {
    asm volatile(
        "mma.sync.aligned.m16n8k16.row.col.f32.f16.f16.f32 "
        "{%0,%1,%2,%3}, {%4,%5,%6,%7}, {%8,%9}, {%0,%1,%2,%3};"
        : "+f"(c[0]), "+f"(c[1]), "+f"(c[2]), "+f"(c[3])
        : "r"(a[0]), "r"(a[1]), "r"(a[2]), "r"(a[3]), "r"(b[0]), "r"(b[1]));
}
__device__ __forceinline__ void ldm4(uint32_t* r, uint32_t addr) {
    asm volatile("ldmatrix.sync.aligned.m8n8.x4.shared.b16 {%0,%1,%2,%3}, [%4];"
                 : "=r"(r[0]), "=r"(r[1]), "=r"(r[2]), "=r"(r[3]) : "r"(addr));
}
__device__ __forceinline__ void ldm4t(uint32_t* r, uint32_t addr) {
    asm volatile("ldmatrix.sync.aligned.m8n8.x4.trans.shared.b16 {%0,%1,%2,%3}, [%4];"
                 : "=r"(r[0]), "=r"(r[1]), "=r"(r[2]), "=r"(r[3]) : "r"(addr));
}
__device__ __forceinline__ uint32_t h22u(__half2 h) {
    return *reinterpret_cast<uint32_t*>(&h);
}

// ---------------------------------------------------------------------------
// Persistent-column fp16 GEMM + bias (R15 version, unchanged).
// ---------------------------------------------------------------------------
template <int BN, bool AHALF, bool OUTHALF, int MAXB>
__global__ __launch_bounds__(256, MAXB)
void gemm_col(const void* __restrict__ Av, const float* __restrict__ Wf,
              const float* __restrict__ bias, void* __restrict__ Cv, int N)
{
    constexpr int WN = BN / 2;
    constexpr int NP = WN / 16;
    constexpr int NT = WN / 8;
    constexpr int WCS = 2576;
    constexpr int AB = 4 * 128 * 20;

    extern __shared__ uint32_t smg[];
    uint32_t* sA = smg;
    uint32_t* sW = smg + AB;

    const int t = threadIdx.x, w = t >> 5, lane = t & 31;
    const int wm = w & 3, wn = w >> 2;
    const int lr = lane >> 2, lc = lane & 3;
    const int lt = lane >> 3, rw = lane & 7;
    const int bn = blockIdx.x * BN;
    const int mbase = blockIdx.y * 128;

    {
        constexpr int WU = (128 * (BN / 8)) / 256;
#pragma unroll
        for (int u = 0; u < WU; u++) {
            int g = t + 256 * u;
            int k = g / (BN / 8), ni = g % (BN / 8);
            const float* Wp = Wf + (size_t)k * N + bn + ni * 8;
            float4 f0 = *(const float4*)(Wp);
            float4 f1 = *(const float4*)(Wp + 4);
            uint4 v;
            v.x = h22u(__floats2half2_rn(f0.x, f0.y));
            v.y = h22u(__floats2half2_rn(f0.z, f0.w));
            v.z = h22u(__floats2half2_rn(f1.x, f1.y));
            v.w = h22u(__floats2half2_rn(f1.z, f1.w));
            *(uint4*)(sW + (ni >> 2) * WCS + k * 20 + (ni & 3) * 4) = v;
        }
    }
#pragma unroll
    for (int u = 0; u < 8; u++) {
        int g = t + 256 * u;
        int s = g >> 9, rem = g & 511;
        int row = rem >> 2, seg = rem & 3;
        uint32_t* dst = sA + s * 2560 + row * 20 + seg * 4;
        if constexpr (!AHALF) {
            const float* Ap = (const float*)Av
                + (size_t)(mbase + row) * 128 + s * 32 + seg * 8;
            float4 f0 = *(const float4*)(Ap);
            float4 f1 = *(const float4*)(Ap + 4);
            uint4 v;
            v.x = h22u(__floats2half2_rn(f0.x, f0.y));
            v.y = h22u(__floats2half2_rn(f0.z, f0.w));
            v.z = h22u(__floats2half2_rn(f1.x, f1.y));
            v.w = h22u(__floats2half2_rn(f1.z, f1.w));
            *(uint4*)dst = v;
        } else {
            const __half* Ap = (const __half*)Av
                + (size_t)(mbase + row) * 128 + s * 32 + seg * 8;
            *(uint4*)dst = *(const uint4*)(Ap);
        }
    }
    __syncthreads();

    const uint32_t smb = (uint32_t)__cvta_generic_to_shared(smg);
    uint32_t aPat[2];
#pragma unroll
    for (int mt = 0; mt < 2; mt++)
        aPat[mt] = ((wm * 32 + mt * 16 + (lt & 1) * 8 + rw) * 20
                    + (lt >> 1) * 4) * 4;
    const uint32_t vpat = ((((lane >> 3) & 1) * 8 + (lane & 7)) * 20
                           + (lane >> 4) * 4) * 4;
    uint32_t bAddr[NP];
#pragma unroll
    for (int p = 0; p < NP; p++) {
        int n0 = wn * WN + p * 16;
        bAddr[p] = smb + (AB + (n0 >> 5) * WCS) * 4 + vpat
                   + ((n0 & 16) ? 32 : 0);
    }
    float bs0[NT], bs1[NT];
#pragma unroll
    for (int nt = 0; nt < NT; nt++) {
        int c = bn + wn * WN + nt * 8 + lc * 2;
        bs0[nt] = bias[c];
        bs1[nt] = bias[c + 1];
    }

    float acc[2][NT][4];
#pragma unroll
    for (int mt = 0; mt < 2; mt++)
#pragma unroll
        for (int nt = 0; nt < NT; nt++)
#pragma unroll
            for (int i = 0; i < 4; i++) acc[mt][nt][i] = 0.f;

#pragma unroll
    for (int s = 0; s < 8; s++) {
        uint32_t af[2][4], bf[NT][2];
        ldm4(af[0], smb + aPat[0] + (s >> 1) * 10240 + (s & 1) * 32);
        ldm4(af[1], smb + aPat[1] + (s >> 1) * 10240 + (s & 1) * 32);
#pragma unroll
        for (int p = 0; p < NP; p++) {
            uint32_t r4[4];
            ldm4t(r4, bAddr[p] + s * 1280);
            bf[2 * p][0] = r4[0]; bf[2 * p][1] = r4[1];
            bf[2 * p + 1][0] = r4[2]; bf[2 * p + 1][1] = r4[3];
        }
#pragma unroll
        for (int mt = 0; mt < 2; mt++)
#pragma unroll
            for (int nt = 0; nt < NT; nt++)
                mma16(acc[mt][nt], af[mt], bf[nt]);
    }

#pragma unroll
    for (int mt = 0; mt < 2; mt++) {
        const int r0 = mbase + wm * 32 + mt * 16 + lr;
#pragma unroll
        for (int nt = 0; nt < NT; nt++) {
            int c = bn + wn * WN + nt * 8 + lc * 2;
            if constexpr (OUTHALF) {
                __half* Ch = (__half*)Cv;
                *(__half2*)(Ch + (size_t)r0 * N + c) =
                    __floats2half2_rn(acc[mt][nt][0] + bs0[nt],
                                      acc[mt][nt][1] + bs1[nt]);
                *(__half2*)(Ch + (size_t)(r0 + 8) * N + c) =
                    __floats2half2_rn(acc[mt][nt][2] + bs0[nt],
                                      acc[mt][nt][3] + bs1[nt]);
            } else {
                float* Cf = (float*)Cv;
                *(float2*)(Cf + (size_t)r0 * N + c) =
                    make_float2(acc[mt][nt][0] + bs0[nt],
                                acc[mt][nt][1] + bs1[nt]);
                *(float2*)(Cf + (size_t)(r0 + 8) * N + c) =
                    make_float2(acc[mt][nt][2] + bs0[nt],
                                acc[mt][nt][3] + bs1[nt]);
            }
        }
    }
}

// ---------------------------------------------------------------------------
// Streaming flash natten v3: valid-row-window loop (4 steps instead of 7).
// For a warp's query pair, valid key rows span [rmin, rmin+7]; the kh-parity
// subset is exactly 4 rows. Steps past row 13 are redirected to a safe,
// fully-masked row (kh). Row masks unchanged -> identical valid-key math.
// ---------------------------------------------------------------------------
#define SQ_OFF 0
#define SK_OFF (64 * 20)                 // 1280
#define SV_OFF (SK_OFF + 224 * 20)       // 5760
#define SM_WORDS (SV_OFF + 224 * 20)     // 10240 words = 40 KB

__global__ __launch_bounds__(256)
void natten_kernel(const __half* __restrict__ qkv, const float* __restrict__ rpb)
{
    __shared__ __align__(16) uint32_t sm[SM_WORDS];
    __shared__ float rp[169];

    const int tile = blockIdx.x;             // 0..48
    const int ti = tile / 7, tj = tile % 7;
    const int h = blockIdx.y, b = blockIdx.z;
    const int i0 = ti * 8, j0 = tj * 8;
    const int r0 = min(max(i0 - 3, 0), HH - 14);
    const int c0 = min(max(j0 - 3, 0), WW - 14);
    const int tid = threadIdx.x;

    for (int e = tid; e < 169; e += 256) rp[e] = rpb[h * 169 + e];

    // Q: 64 rows x 32 halves (one uint4 per thread)
    {
        int row = tid >> 2, seg = tid & 3;
        int qi = row >> 3, qj = row & 7;
        size_t pix = (size_t)((b * HH + i0 + qi) * WW + j0 + qj);
        *(uint4*)(sm + SQ_OFF + row * 20 + seg * 4) =
            *(const uint4*)(qkv + pix * 384 + h * 32 + seg * 8);
    }
    // K and V: 196 real window rows into padded [r*16+c] positions
    for (int e = tid; e < 784; e += 256) {
        int pos = e >> 2, seg = e & 3;
        int r = pos / 14, c = pos - r * 14;
        size_t pix = (size_t)((b * HH + r0 + r) * WW + c0 + c);
        const __half* base = qkv + pix * 384 + h * 32;
        int off = (r * 16 + c) * 20 + seg * 4;
        *(uint4*)(sm + SK_OFF + off) = *(const uint4*)(base + 128 + seg * 8);
        *(uint4*)(sm + SV_OFF + off) = *(const uint4*)(base + 256 + seg * 8);
    }
    // zero pad columns c = 14,15 of each of 14 rows (448 words each tensor)
    for (int e = tid; e < 448; e += 256) {
        int p = e >> 4, wd = e & 15;
        int off = ((p >> 1) * 16 + 14 + (p & 1)) * 20 + wd;
        sm[SK_OFF + off] = 0;
        sm[SV_OFF + off] = 0;
    }
    __syncthreads();

    const int w = tid >> 5, lane = tid & 31;
    const int qw = w & 3, kh = w >> 2;
    const int lr = lane >> 2, lc = lane & 3;
    const int lt = lane >> 3, rw = lane & 7;

    const uint32_t base = (uint32_t)__cvta_generic_to_shared(sm);
    const uint32_t aAddr = base + SQ_OFF * 4
        + ((qw * 16 + (lt & 1) * 8 + rw) * 20 + ((lt >> 1) << 2)) * 4;
    const uint32_t kAddr = base + SK_OFF * 4
        + ((((lt >> 1) << 3) + rw) * 20 + ((lt & 1) << 2)) * 4;
    const uint32_t vAddr = base + SV_OFF * 4
        + (((((lane >> 3) & 1) << 3) + (lane & 7)) * 20 + ((lane >> 4) << 2)) * 4;

    uint32_t af0[4], af1[4];
    ldm4(af0, aAddr);
    ldm4(af1, aAddr + 32);

    const int i_lo = i0 + 2 * qw, i_hi = i_lo + 1;
    const int j = j0 + lr;
    const int kri_lo = min(max(i_lo - 3, 0), HH - 7) - r0;
    const int kri_hi = min(max(i_hi - 3, 0), HH - 7) - r0;
    const int kcj = min(max(j - 3, 0), WW - 7) - c0;
    const int ci_lo = 6 - (i_lo - r0);
    const int ci_hi = 6 - (i_hi - r0);
    const int cj = 6 - (j - c0);
    const float scale = 0.17677669529663687f;   // 32^-0.5

    // hoisted per-key-column constants (kc fixed per (tt,c))
    bool vC[2][2];
    int  cb[2][2];
#pragma unroll
    for (int tt = 0; tt < 2; tt++)
#pragma unroll
        for (int c = 0; c < 2; c++) {
            int kc = tt * 8 + 2 * lc + c;
            vC[tt][c] = (unsigned)(kc - kcj) < 7u;
            cb[tt][c] = kc + cj;
        }

    float out[4][4];
#pragma unroll
    for (int nt = 0; nt < 4; nt++)
#pragma unroll
        for (int i = 0; i < 4; i++) out[nt][i] = 0.f;
    float l_lo = 0.f, l_hi = 0.f;

    // valid key rows for this warp's query pair: [rmin, rmin+7];
    // kh-parity subset = exactly 4 rows starting at t0.
    const int rmin = min(kri_lo, kri_hi);
    const int t0 = rmin + ((rmin ^ kh) & 1);

#pragma unroll
    for (int st = 0; st < 4; st++) {
        int t2 = t0 + 2 * st;
        if (t2 > 13) t2 = kh;                   // safe fully-masked row
        const uint32_t aoff = (uint32_t)t2 * 1280;

        float sacc[2][4];
#pragma unroll
        for (int tt = 0; tt < 2; tt++)
#pragma unroll
            for (int i = 0; i < 4; i++) sacc[tt][i] = 0.f;
        {
            uint32_t r4[4];
            ldm4(r4, kAddr + aoff);
            mma16(sacc[0], af0, r4);
            mma16(sacc[1], af0, r4 + 2);
            ldm4(r4, kAddr + aoff + 32);
            mma16(sacc[0], af1, r4);
            mma16(sacc[1], af1, r4 + 2);
        }

        const bool rok_lo = (unsigned)(t2 - kri_lo) < 7u;
        const bool rok_hi = (unsigned)(t2 - kri_hi) < 7u;
        const int rb_lo = (t2 + ci_lo) * 13;
        const int rb_hi = (t2 + ci_hi) * 13;

        uint32_t pa[4];
#pragma unroll
        for (int tt = 0; tt < 2; tt++) {
#pragma unroll
            for (int c = 0; c < 2; c++) {
                bool ok1 = rok_lo && vC[tt][c];
                int idx1 = min(max(rb_lo + cb[tt][c], 0), 168);
                float e1 = __expf(ok1 ? fmaf(sacc[tt][c], scale, rp[idx1]) : -60.f);
                sacc[tt][c] = e1;
                l_lo += e1;

                bool ok2 = rok_hi && vC[tt][c];
                int idx2 = min(max(rb_hi + cb[tt][c], 0), 168);
                float e2 = __expf(ok2 ? fmaf(sacc[tt][2 + c], scale, rp[idx2]) : -60.f);
                sacc[tt][2 + c] = e2;
                l_hi += e2;
            }
        }
        pa[0] = h22u(__floats2half2_rn(sacc[0][0], sacc[0][1]));
        pa[1] = h22u(__floats2half2_rn(sacc[0][2], sacc[0][3]));
        pa[2] = h22u(__floats2half2_rn(sacc[1][0], sacc[1][1]));
        pa[3] = h22u(__floats2half2_rn(sacc[1][2], sacc[1][3]));

        uint32_t b0[4], b1[4];
        ldm4t(b0, vAddr + aoff);
        ldm4t(b1, vAddr + aoff + 32);
        mma16(out[0], pa, b0);
        mma16(out[1], pa, b0 + 2);
        mma16(out[2], pa, b1);
        mma16(out[3], pa, b1 + 2);
    }

    // ---- cross-warp combine (kh=1 -> staging -> kh=0 adds) ----
    __syncthreads();                       // K region dead; reuse as staging
    float* stg = (float*)(sm + SK_OFF);
    const int sl = (qw * 32 + lane) * 19;
    if (kh == 1) {
#pragma unroll
        for (int nt = 0; nt < 4; nt++)
#pragma unroll
            for (int i = 0; i < 4; i++) stg[sl + nt * 4 + i] = out[nt][i];
        stg[sl + 16] = l_lo;
        stg[sl + 17] = l_hi;
    }
    __syncthreads();

    if (kh == 0) {
#pragma unroll
        for (int nt = 0; nt < 4; nt++)
#pragma unroll
            for (int i = 0; i < 4; i++) out[nt][i] += stg[sl + nt * 4 + i];
        l_lo += stg[sl + 16];
        l_hi += stg[sl + 17];

        const unsigned fm = 0xffffffffu;
        l_lo += __shfl_xor_sync(fm, l_lo, 1);
        l_lo += __shfl_xor_sync(fm, l_lo, 2);
        l_hi += __shfl_xor_sync(fm, l_hi, 1);
        l_hi += __shfl_xor_sync(fm, l_hi, 2);

        const float inv_lo = __frcp_rn(l_lo);
        const float inv_hi = __frcp_rn(l_hi);
        __half* o_lo = g_att + ((size_t)((b * HH + i_lo) * WW + j)) * 128 + h * 32;
        __half* o_hi = g_att + ((size_t)((b * HH + i_hi) * WW + j)) * 128 + h * 32;
#pragma unroll
        for (int nt = 0; nt < 4; nt++) {
            *(__half2*)(o_lo + nt * 8 + 2 * lc) =
                __floats2half2_rn(out[nt][0] * inv_lo, out[nt][1] * inv_lo);
            *(__half2*)(o_hi + nt * 8 + 2 * lc) =
                __floats2half2_rn(out[nt][2] * inv_hi, out[nt][3] * inv_hi);
        }
    }
}

// ---------------------------------------------------------------------------
// Launch
// ---------------------------------------------------------------------------
extern "C" void kernel_launch(void* const* d_in, const int* in_sizes, int n_in,
                              void* d_out, int out_size)
{
    const float* x      = (const float*)d_in[0];  // [4,56,56,128]
    const float* w_qkv  = (const float*)d_in[1];  // [128,384]
    const float* b_qkv  = (const float*)d_in[2];  // [384]
    const float* rpb    = (const float*)d_in[3];  // [4,13,13]
    const float* w_proj = (const float*)d_in[4];  // [128,128]
    const float* b_proj = (const float*)d_in[5];  // [128]
    float* out = (float*)d_out;                   // [4,56,56,128] fp32
    (void)in_sizes; (void)n_in; (void)out_size;

    __half *qkv_buf, *att_buf;
    cudaGetSymbolAddress((void**)&qkv_buf, g_qkv);
    cudaGetSymbolAddress((void**)&att_buf, g_att);

    constexpr int SMQ = (4 * 128 * 20 + 4 * 2576) * 4;   // 82176 B
    constexpr int SMP = (4 * 128 * 20 + 2 * 2576) * 4;   // 61568 B

    cudaFuncSetAttribute((const void*)gemm_col<128, false, true, 2>,
                         cudaFuncAttributeMaxDynamicSharedMemorySize, SMQ);
    cudaFuncSetAttribute((const void*)gemm_col<64, true, false, 3>,
                         cudaFuncAttributeMaxDynamicSharedMemorySize, SMP);

    // 1) QKV projection: [12544,128] @ [128,384] + b_qkv -> half
    gemm_col<128, false, true, 2><<<dim3(3, 98), 256, SMQ>>>(
        x, w_qkv, b_qkv, qkv_buf, 384);

    // 2) Neighborhood attention (valid-row-window, 4 steps/warp)
    natten_kernel<<<dim3(49, 4, 4), 256>>>(qkv_buf, rpb);

    // 3) Output projection: [12544,128] @ [128,128] + b_proj -> float
    gemm_col<64, true, false, 3><<<dim3(2, 98), 256, SMP>>>(
        att_buf, w_proj, b_proj, out, 128);
}